// round 1
// baseline (speedup 1.0000x reference)
#include <cuda_runtime.h>
#include <math.h>

// Problem constants
#define B_ 4
#define L_ 2048
#define D_ 1024
#define H_ 16
#define DK_ 64
#define M_ (B_ * L_)      // 8192
#define N1_ (3 * D_)      // 3072

// Scratch (device globals: allocation-free per harness rules)
__device__ float g_qkv[(size_t)M_ * N1_];   // 8192 x 3072
__device__ float g_ctx[(size_t)M_ * D_];    // 8192 x 1024

// ---------------------------------------------------------------------------
// Tiled SGEMM with bias: C[M,N] = A[M,K] @ B[K,N] + bias[N]
// BM=BN=128, BK=16, 8x8 microtile, 256 threads
// ---------------------------------------------------------------------------
__global__ __launch_bounds__(256) void sgemm_bias_kernel(
    int M, int N, int K,
    const float* __restrict__ A,
    const float* __restrict__ Bw,
    const float* __restrict__ bias,
    float* __restrict__ C)
{
    constexpr int BM = 128, BN = 128, BK = 16, TM = 8, TN = 8;
    __shared__ float As[BK][BM];   // stored transposed: As[k][m]
    __shared__ float Bs[BK][BN];

    const int tid = threadIdx.x;
    const int threadCol = tid % (BN / TN);   // 0..15
    const int threadRow = tid / (BN / TN);   // 0..15

    const float* Ab = A + (size_t)blockIdx.y * BM * K;
    const float* Bb = Bw + (size_t)blockIdx.x * BN;
    float* Cb = C + (size_t)blockIdx.y * BM * N + (size_t)blockIdx.x * BN;

    const int iRA = tid / 4;          // 0..63
    const int iCA = (tid % 4) * 4;    // 0,4,8,12
    const int iRB = tid / 32;         // 0..7
    const int iCB = (tid % 32) * 4;   // 0..124

    float res[TM][TN];
#pragma unroll
    for (int i = 0; i < TM; i++)
#pragma unroll
        for (int j = 0; j < TN; j++) res[i][j] = 0.0f;

    for (int bk = 0; bk < K; bk += BK) {
#pragma unroll
        for (int r = 0; r < BM; r += 64) {
            float4 t = *reinterpret_cast<const float4*>(Ab + (size_t)(iRA + r) * K + iCA);
            As[iCA + 0][iRA + r] = t.x;
            As[iCA + 1][iRA + r] = t.y;
            As[iCA + 2][iRA + r] = t.z;
            As[iCA + 3][iRA + r] = t.w;
        }
#pragma unroll
        for (int r = 0; r < BK; r += 8) {
            *reinterpret_cast<float4*>(&Bs[iRB + r][iCB]) =
                *reinterpret_cast<const float4*>(Bb + (size_t)(iRB + r) * N + iCB);
        }
        __syncthreads();
        Ab += BK;
        Bb += (size_t)BK * N;

#pragma unroll
        for (int k = 0; k < BK; k++) {
            float regM[TM], regN[TN];
            *reinterpret_cast<float4*>(regM)     = *reinterpret_cast<float4*>(&As[k][threadRow * TM]);
            *reinterpret_cast<float4*>(regM + 4) = *reinterpret_cast<float4*>(&As[k][threadRow * TM + 4]);
            *reinterpret_cast<float4*>(regN)     = *reinterpret_cast<float4*>(&Bs[k][threadCol * TN]);
            *reinterpret_cast<float4*>(regN + 4) = *reinterpret_cast<float4*>(&Bs[k][threadCol * TN + 4]);
#pragma unroll
            for (int i = 0; i < TM; i++)
#pragma unroll
                for (int j = 0; j < TN; j++)
                    res[i][j] += regM[i] * regN[j];
        }
        __syncthreads();
    }

#pragma unroll
    for (int i = 0; i < TM; i++) {
#pragma unroll
        for (int j4 = 0; j4 < TN; j4 += 4) {
            float4 bv = *reinterpret_cast<const float4*>(
                bias + (size_t)blockIdx.x * BN + threadCol * TN + j4);
            float4 o;
            o.x = res[i][j4 + 0] + bv.x;
            o.y = res[i][j4 + 1] + bv.y;
            o.z = res[i][j4 + 2] + bv.z;
            o.w = res[i][j4 + 3] + bv.w;
            *reinterpret_cast<float4*>(
                Cb + (size_t)(threadRow * TM + i) * N + threadCol * TN + j4) = o;
        }
    }
}

// ---------------------------------------------------------------------------
// Flash-style masked attention, fp32.
// One block = one (b,h) pair and a 64-row Q tile. 256 threads = 16x16 grid,
// each thread owns a 4(q) x 4(k / d) microtile.
//
// Masked-softmax semantics (faithful to reference):
//   masked score -> 0.0f participates in max & denominator;
//   masked probability -> 0 in the numerator (P·V).
// ---------------------------------------------------------------------------
__global__ __launch_bounds__(256) void flash_attn_kernel(
    const float* __restrict__ qkv,
    const int*   __restrict__ mask,
    float* __restrict__ ctx)
{
    extern __shared__ float smem_[];
    float (*Qs)[65] = reinterpret_cast<float(*)[65]>(smem_);              // 64x65
    float (*Ks)[65] = reinterpret_cast<float(*)[65]>(smem_ + 64 * 65);    // 64x65 (reused for P)
    float (*Vs)[64] = reinterpret_cast<float(*)[64]>(smem_ + 2 * 64 * 65);// 64x64

    const int bh = blockIdx.y;
    const int b  = bh >> 4;        // / H
    const int h  = bh & 15;
    const int q0 = blockIdx.x * 64;
    const int tid = threadIdx.x;
    const int tr = tid >> 4;       // 0..15  (q-row group)
    const int tc = tid & 15;       // 0..15  (k-col / d-col group)

    const float* qb = qkv + ((size_t)(b * L_ + q0)) * N1_ + h * DK_;
    const float* kb = qkv + ((size_t)(b * L_)) * N1_ + D_     + h * DK_;
    const float* vb = qkv + ((size_t)(b * L_)) * N1_ + 2 * D_ + h * DK_;
    const int*   mb = mask + (size_t)b * L_ * L_ + (size_t)q0 * L_;

    // Load Q tile (64 x 64)
#pragma unroll
    for (int i = 0; i < 4; i++) {
        int f   = tid + i * 256;
        int row = f >> 4;
        int c4  = (f & 15) * 4;
        float4 v = *reinterpret_cast<const float4*>(qb + (size_t)row * N1_ + c4);
        Qs[row][c4 + 0] = v.x; Qs[row][c4 + 1] = v.y;
        Qs[row][c4 + 2] = v.z; Qs[row][c4 + 3] = v.w;
    }

    float mrow[4], lrow[4], acc[4][4];
#pragma unroll
    for (int i = 0; i < 4; i++) {
        mrow[i] = -INFINITY;
        lrow[i] = 0.0f;
#pragma unroll
        for (int j = 0; j < 4; j++) acc[i][j] = 0.0f;
    }
    __syncthreads();

    for (int t = 0; t < 32; t++) {
        const int k0 = t * 64;

        // Load K,V tiles (64x64 each), coalesced float4
#pragma unroll
        for (int i = 0; i < 4; i++) {
            int f   = tid + i * 256;
            int row = f >> 4;
            int c4  = (f & 15) * 4;
            float4 kv4 = *reinterpret_cast<const float4*>(kb + (size_t)(k0 + row) * N1_ + c4);
            Ks[row][c4 + 0] = kv4.x; Ks[row][c4 + 1] = kv4.y;
            Ks[row][c4 + 2] = kv4.z; Ks[row][c4 + 3] = kv4.w;
            float4 vv4 = *reinterpret_cast<const float4*>(vb + (size_t)(k0 + row) * N1_ + c4);
            *reinterpret_cast<float4*>(&Vs[row][c4]) = vv4;
        }
        __syncthreads();

        // S = Q K^T  (4x4 microtile per thread)
        float s[4][4];
#pragma unroll
        for (int i = 0; i < 4; i++)
#pragma unroll
            for (int j = 0; j < 4; j++) s[i][j] = 0.0f;

#pragma unroll
        for (int k = 0; k < 64; k++) {
            float qv[4], kv[4];
#pragma unroll
            for (int i = 0; i < 4; i++) qv[i] = Qs[tr * 4 + i][k];
#pragma unroll
            for (int j = 0; j < 4; j++) kv[j] = Ks[tc * 4 + j][k];
#pragma unroll
            for (int i = 0; i < 4; i++)
#pragma unroll
                for (int j = 0; j < 4; j++)
                    s[i][j] += qv[i] * kv[j];
        }

        // Mask + scale + online softmax update
        float p[4][4], mnew[4], lsum[4];
#pragma unroll
        for (int i = 0; i < 4; i++) {
            const int4 mv = *reinterpret_cast<const int4*>(
                mb + (size_t)(tr * 4 + i) * L_ + k0 + tc * 4);
            float s0 = mv.x ? s[i][0] * 0.125f : 0.0f;   // masked -> 0.0 (DBL_MIN underflow)
            float s1 = mv.y ? s[i][1] * 0.125f : 0.0f;
            float s2 = mv.z ? s[i][2] * 0.125f : 0.0f;
            float s3 = mv.w ? s[i][3] * 0.125f : 0.0f;

            float tm = fmaxf(fmaxf(s0, s1), fmaxf(s2, s3));
            tm = fmaxf(tm, __shfl_xor_sync(0xffffffffu, tm, 1));
            tm = fmaxf(tm, __shfl_xor_sync(0xffffffffu, tm, 2));
            tm = fmaxf(tm, __shfl_xor_sync(0xffffffffu, tm, 4));
            tm = fmaxf(tm, __shfl_xor_sync(0xffffffffu, tm, 8));
            mnew[i] = fmaxf(mrow[i], tm);

            float e0 = __expf(s0 - mnew[i]);
            float e1 = __expf(s1 - mnew[i]);
            float e2 = __expf(s2 - mnew[i]);
            float e3 = __expf(s3 - mnew[i]);
            float ls = e0 + e1 + e2 + e3;            // denominator includes masked terms
            ls += __shfl_xor_sync(0xffffffffu, ls, 1);
            ls += __shfl_xor_sync(0xffffffffu, ls, 2);
            ls += __shfl_xor_sync(0xffffffffu, ls, 4);
            ls += __shfl_xor_sync(0xffffffffu, ls, 8);
            lsum[i] = ls;

            p[i][0] = mv.x ? e0 : 0.0f;              // numerator zeroed where masked
            p[i][1] = mv.y ? e1 : 0.0f;
            p[i][2] = mv.z ? e2 : 0.0f;
            p[i][3] = mv.w ? e3 : 0.0f;
        }

        __syncthreads();   // everyone done reading Ks before P overwrites it

        // Store P into the K buffer
#pragma unroll
        for (int i = 0; i < 4; i++)
#pragma unroll
            for (int j = 0; j < 4; j++)
                Ks[tr * 4 + i][tc * 4 + j] = p[i][j];

        // Rescale accumulators & update running stats
#pragma unroll
        for (int i = 0; i < 4; i++) {
            float sc = __expf(mrow[i] - mnew[i]);   // exp(-inf)=0 on first tile
            lrow[i] = lrow[i] * sc + lsum[i];
            mrow[i] = mnew[i];
#pragma unroll
            for (int j = 0; j < 4; j++) acc[i][j] *= sc;
        }
        __syncthreads();   // P visible to all

        // O += P @ V   (4x4 microtile; V read via float4)
#pragma unroll
        for (int k = 0; k < 64; k++) {
            float pv[4];
#pragma unroll
            for (int i = 0; i < 4; i++) pv[i] = Ks[tr * 4 + i][k];
            float4 vvf = *reinterpret_cast<const float4*>(&Vs[k][tc * 4]);
#pragma unroll
            for (int i = 0; i < 4; i++) {
                acc[i][0] += pv[i] * vvf.x;
                acc[i][1] += pv[i] * vvf.y;
                acc[i][2] += pv[i] * vvf.z;
                acc[i][3] += pv[i] * vvf.w;
            }
        }
        __syncthreads();   // done with Ks/Vs before next tile load
    }

    // Normalize and write ctx[b, q, h, d]
    float* ob = ctx + ((size_t)(b * L_ + q0)) * D_ + h * DK_;
#pragma unroll
    for (int i = 0; i < 4; i++) {
        float inv = 1.0f / lrow[i];
        float4 o;
        o.x = acc[i][0] * inv;
        o.y = acc[i][1] * inv;
        o.z = acc[i][2] * inv;
        o.w = acc[i][3] * inv;
        *reinterpret_cast<float4*>(ob + (size_t)(tr * 4 + i) * D_ + tc * 4) = o;
    }
}

// ---------------------------------------------------------------------------
// kernel_launch: GEMM1 (QKV) -> flash attention -> GEMM2 (output proj)
// ---------------------------------------------------------------------------
extern "C" void kernel_launch(void* const* d_in, const int* in_sizes, int n_in,
                              void* d_out, int out_size)
{
    const float* inputs = (const float*)d_in[0];
    const int*   mask   = (const int*)d_in[1];
    const float* W1     = (const float*)d_in[2];
    const float* b1     = (const float*)d_in[3];
    const float* W2     = (const float*)d_in[4];
    const float* b2     = (const float*)d_in[5];
    float* out = (float*)d_out;

    float* qkv = nullptr;
    float* ctx = nullptr;
    cudaGetSymbolAddress((void**)&qkv, g_qkv);
    cudaGetSymbolAddress((void**)&ctx, g_ctx);

    const int attn_smem = (2 * 64 * 65 + 64 * 64) * (int)sizeof(float);  // 49664 B
    cudaFuncSetAttribute(flash_attn_kernel,
                         cudaFuncAttributeMaxDynamicSharedMemorySize, attn_smem);

    dim3 blk(256);
    // GEMM1: (8192 x 3072) = inputs @ W1 + b1
    sgemm_bias_kernel<<<dim3(N1_ / 128, M_ / 128), blk>>>(M_, N1_, D_, inputs, W1, b1, qkv);
    // Attention: 32 q-tiles x 64 (b,h) blocks
    flash_attn_kernel<<<dim3(L_ / 64, B_ * H_), blk, attn_smem>>>(qkv, mask, ctx);
    // GEMM2: (8192 x 1024) = ctx @ W2 + b2
    sgemm_bias_kernel<<<dim3(D_ / 128, M_ / 128), blk>>>(M_, D_, D_, ctx, W2, b2, out);
}

// round 3
// speedup vs baseline: 1.1995x; 1.1995x over previous
#include <cuda_runtime.h>
#include <cuda_bf16.h>
#include <math.h>
#include <stdint.h>

// Problem constants
#define B_ 4
#define L_ 2048
#define D_ 1024
#define H_ 16
#define DK_ 64
#define M_ (B_ * L_)      // 8192
#define N1_ (3 * D_)      // 3072
#define K3_ 3072          // split-bf16 K' = 3*1024

// Scratch (device globals: allocation-free per harness rules)
__device__ float g_qkv[(size_t)M_ * N1_];            // 8192 x 3072 fp32
__device__ float g_ctx[(size_t)M_ * D_];             // 8192 x 1024 fp32
__device__ __nv_bfloat16 g_Abf[(size_t)M_ * K3_];    // 8192 x 3072 bf16 (A split)
__device__ __nv_bfloat16 g_Bbf[(size_t)N1_ * K3_];   // up to 3072 x 3072 bf16 (B^T split)

__device__ __forceinline__ uint32_t smem_u32(const void* p) {
    uint32_t a;
    asm("{ .reg .u64 t; cvta.to.shared.u64 t, %1; cvt.u32.u64 %0, t; }" : "=r"(a) : "l"(p));
    return a;
}
#define LDMATRIX_X4(r0, r1, r2, r3, addr) \
    asm volatile("ldmatrix.sync.aligned.m8n8.x4.shared.b16 {%0,%1,%2,%3}, [%4];" \
                 : "=r"(r0), "=r"(r1), "=r"(r2), "=r"(r3) : "r"(addr))
#define MMA_BF16(d, a, b0, b1) \
    asm volatile("mma.sync.aligned.m16n8k16.row.col.f32.bf16.bf16.f32 " \
                 "{%0,%1,%2,%3}, {%4,%5,%6,%7}, {%8,%9}, {%0,%1,%2,%3};" \
                 : "+f"((d)[0]), "+f"((d)[1]), "+f"((d)[2]), "+f"((d)[3]) \
                 : "r"((a)[0]), "r"((a)[1]), "r"((a)[2]), "r"((a)[3]), \
                   "r"(b0), "r"(b1))

// ===========================================================================
// Split-bf16 pack kernels
//   A'[m] = [hi(k) | lo(k) | hi(k)]  (K=1024 -> K'=3072)
//   B'^T[n] = [hi(k) | hi(k) | lo(k)]
// ===========================================================================
__global__ __launch_bounds__(256) void pack_a_kernel(
    const float* __restrict__ X, __nv_bfloat16* __restrict__ A2)
{
    int i = (blockIdx.x * 256 + threadIdx.x) * 4;     // over M_*1024 elements
    int m = i >> 10;
    int k = i & 1023;
    float4 v = *reinterpret_cast<const float4*>(X + i);

    __nv_bfloat16 h0 = __float2bfloat16(v.x), h1 = __float2bfloat16(v.y);
    __nv_bfloat16 h2 = __float2bfloat16(v.z), h3 = __float2bfloat16(v.w);
    __nv_bfloat16 l0 = __float2bfloat16(v.x - __bfloat162float(h0));
    __nv_bfloat16 l1 = __float2bfloat16(v.y - __bfloat162float(h1));
    __nv_bfloat16 l2 = __float2bfloat16(v.z - __bfloat162float(h2));
    __nv_bfloat16 l3 = __float2bfloat16(v.w - __bfloat162float(h3));

    size_t ro = (size_t)m * K3_;
    __nv_bfloat162 hA; hA.x = h0; hA.y = h1;
    __nv_bfloat162 hB; hB.x = h2; hB.y = h3;
    __nv_bfloat162 lA; lA.x = l0; lA.y = l1;
    __nv_bfloat162 lB; lB.x = l2; lB.y = l3;

    __nv_bfloat162* p0 = reinterpret_cast<__nv_bfloat162*>(A2 + ro + k);
    p0[0] = hA; p0[1] = hB;
    __nv_bfloat162* p1 = reinterpret_cast<__nv_bfloat162*>(A2 + ro + 1024 + k);
    p1[0] = lA; p1[1] = lB;
    __nv_bfloat162* p2 = reinterpret_cast<__nv_bfloat162*>(A2 + ro + 2048 + k);
    p2[0] = hA; p2[1] = hB;
}

// W (K x N) fp32 -> Bt (N x K3_) bf16 with [hi, hi, lo] segments (K=1024)
__global__ void pack_bt_kernel(
    const float* __restrict__ W, __nv_bfloat16* __restrict__ Bt, int N)
{
    __shared__ float ts[32][33];
    int n0 = blockIdx.x * 32, k0 = blockIdx.y * 32;
    int tx = threadIdx.x, ty = threadIdx.y;   // (32, 8)
#pragma unroll
    for (int r = 0; r < 32; r += 8)
        ts[ty + r][tx] = W[(size_t)(k0 + ty + r) * N + n0 + tx];
    __syncthreads();
#pragma unroll
    for (int r = 0; r < 32; r += 8) {
        int n = n0 + ty + r;
        int k = k0 + tx;
        float x = ts[tx][ty + r];
        __nv_bfloat16 hi = __float2bfloat16(x);
        __nv_bfloat16 lo = __float2bfloat16(x - __bfloat162float(hi));
        size_t ro = (size_t)n * K3_;
        Bt[ro + k]        = hi;
        Bt[ro + 1024 + k] = hi;
        Bt[ro + 2048 + k] = lo;
    }
}

// ===========================================================================
// HMMA (mma.sync bf16) GEMM:  C[M,N] = A2[M,K3] @ Bt[N,K3]^T + bias[N]
// CTA tile 128x128, BK=32, double-buffered smem, 8 warps (4m x 2n),
// warp tile 32x64 built from m16n8k16 atoms.
// ===========================================================================
__global__ __launch_bounds__(256) void mma_gemm_kernel(
    const __nv_bfloat16* __restrict__ A2,
    const __nv_bfloat16* __restrict__ Bt,
    const float* __restrict__ bias,
    float* __restrict__ C, int N)
{
    // padded rows: 40 bf16 = 80B stride -> conflict-free ldmatrix
    __shared__ __nv_bfloat16 As[2][128][40];
    __shared__ __nv_bfloat16 Bs[2][128][40];

    const int tid  = threadIdx.x;
    const int lane = tid & 31;
    const int wid  = tid >> 5;
    const int wm   = wid & 3;       // 0..3 -> 32-row slab
    const int wn   = wid >> 2;      // 0..1 -> 64-col slab
    const int bm = blockIdx.y, bn = blockIdx.x;

    const __nv_bfloat16* Ag = A2 + (size_t)(bm * 128) * K3_;
    const __nv_bfloat16* Bg = Bt + (size_t)(bn * 128) * K3_;

    const uint32_t aBase = smem_u32(&As[0][0][0]);
    const uint32_t bBase = smem_u32(&Bs[0][0][0]);
    const uint32_t BUFB = 128 * 40 * 2;    // 10240 bytes per buffer

    // ldmatrix lane addressing (byte offsets within a buffer)
    const uint32_t aRowOff = (uint32_t)(wm * 32 + (lane & 15)) * 80 + (uint32_t)(lane >> 4) * 16;
    const uint32_t bRowOff0 = (uint32_t)(wn * 64 + ((lane >> 3) * 8) + (lane & 7)) * 80;

    float acc[2][8][4];
#pragma unroll
    for (int i = 0; i < 2; i++)
#pragma unroll
        for (int j = 0; j < 8; j++)
#pragma unroll
            for (int q = 0; q < 4; q++) acc[i][j][q] = 0.0f;

    const int NC = K3_ / 32;   // 96 chunks

    uint4 ra[2], rb[2];
    // ldg index: 512 float4 per operand tile; row = idx>>2, seg = idx&3
    const int r0 = tid >> 2, s0 = (tid & 3) * 8;
    const int r1 = (tid + 256) >> 2, s1 = ((tid + 256) & 3) * 8;

    auto LDG = [&](int c) {
        const __nv_bfloat16* a0 = Ag + (size_t)r0 * K3_ + c * 32 + s0;
        const __nv_bfloat16* a1 = Ag + (size_t)r1 * K3_ + c * 32 + s1;
        const __nv_bfloat16* b0 = Bg + (size_t)r0 * K3_ + c * 32 + s0;
        const __nv_bfloat16* b1 = Bg + (size_t)r1 * K3_ + c * 32 + s1;
        ra[0] = *reinterpret_cast<const uint4*>(a0);
        ra[1] = *reinterpret_cast<const uint4*>(a1);
        rb[0] = *reinterpret_cast<const uint4*>(b0);
        rb[1] = *reinterpret_cast<const uint4*>(b1);
    };
    auto STS = [&](int buf) {
        *reinterpret_cast<uint4*>(&As[buf][r0][s0]) = ra[0];
        *reinterpret_cast<uint4*>(&As[buf][r1][s1]) = ra[1];
        *reinterpret_cast<uint4*>(&Bs[buf][r0][s0]) = rb[0];
        *reinterpret_cast<uint4*>(&Bs[buf][r1][s1]) = rb[1];
    };

    LDG(0);
    STS(0);
    __syncthreads();

    for (int c = 0; c < NC; c++) {
        if (c + 1 < NC) LDG(c + 1);
        const int buf = c & 1;
        const uint32_t aB = aBase + buf * BUFB;
        const uint32_t bB = bBase + buf * BUFB;

#pragma unroll
        for (int s = 0; s < 2; s++) {          // two k16 steps
            uint32_t aF[2][4];
#pragma unroll
            for (int mi = 0; mi < 2; mi++) {
                uint32_t addr = aB + aRowOff + (uint32_t)(mi * 16) * 80 + s * 32;
                LDMATRIX_X4(aF[mi][0], aF[mi][1], aF[mi][2], aF[mi][3], addr);
            }
            uint32_t bF0[8], bF1[8];
#pragma unroll
            for (int g = 0; g < 2; g++) {
                uint32_t addr = bB + bRowOff0 + (uint32_t)(g * 32) * 80 + s * 32;
                LDMATRIX_X4(bF0[g*4+0], bF0[g*4+1], bF0[g*4+2], bF0[g*4+3], addr);
                LDMATRIX_X4(bF1[g*4+0], bF1[g*4+1], bF1[g*4+2], bF1[g*4+3], addr + 16);
            }
#pragma unroll
            for (int mi = 0; mi < 2; mi++)
#pragma unroll
                for (int nj = 0; nj < 8; nj++)
                    MMA_BF16(acc[mi][nj], aF[mi], bF0[nj], bF1[nj]);
        }

        __syncthreads();
        if (c + 1 < NC) {
            STS((c + 1) & 1);
            __syncthreads();
        }
    }

    // Epilogue: fragment layout m16n8 -> (row = lane/4 [+8], col = 2*(lane%4))
    const int qr = lane >> 2;
    const int qc = (lane & 3) * 2;
#pragma unroll
    for (int mi = 0; mi < 2; mi++) {
        int row = bm * 128 + wm * 32 + mi * 16 + qr;
#pragma unroll
        for (int nj = 0; nj < 8; nj++) {
            int col = bn * 128 + wn * 64 + nj * 8 + qc;
            float bv0 = __ldg(bias + col);
            float bv1 = __ldg(bias + col + 1);
            float2 o0, o1;
            o0.x = acc[mi][nj][0] + bv0;
            o0.y = acc[mi][nj][1] + bv1;
            o1.x = acc[mi][nj][2] + bv0;
            o1.y = acc[mi][nj][3] + bv1;
            *reinterpret_cast<float2*>(C + (size_t)row * N + col) = o0;
            *reinterpret_cast<float2*>(C + (size_t)(row + 8) * N + col) = o1;
        }
    }
}

// ===========================================================================
// Flash-style masked attention, fp32 (proven; next round's HMMA target)
// ===========================================================================
__global__ __launch_bounds__(256) void flash_attn_kernel(
    const float* __restrict__ qkv,
    const int*   __restrict__ mask,
    float* __restrict__ ctx)
{
    extern __shared__ float smem_[];
    float (*Qs)[65] = reinterpret_cast<float(*)[65]>(smem_);
    float (*Ks)[65] = reinterpret_cast<float(*)[65]>(smem_ + 64 * 65);
    float (*Vs)[64] = reinterpret_cast<float(*)[64]>(smem_ + 2 * 64 * 65);

    const int bh = blockIdx.y;
    const int b  = bh >> 4;
    const int h  = bh & 15;
    const int q0 = blockIdx.x * 64;
    const int tid = threadIdx.x;
    const int tr = tid >> 4;
    const int tc = tid & 15;

    const float* qb = qkv + ((size_t)(b * L_ + q0)) * N1_ + h * DK_;
    const float* kb = qkv + ((size_t)(b * L_)) * N1_ + D_     + h * DK_;
    const float* vb = qkv + ((size_t)(b * L_)) * N1_ + 2 * D_ + h * DK_;
    const int*   mb = mask + (size_t)b * L_ * L_ + (size_t)q0 * L_;

#pragma unroll
    for (int i = 0; i < 4; i++) {
        int f   = tid + i * 256;
        int row = f >> 4;
        int c4  = (f & 15) * 4;
        float4 v = *reinterpret_cast<const float4*>(qb + (size_t)row * N1_ + c4);
        Qs[row][c4 + 0] = v.x; Qs[row][c4 + 1] = v.y;
        Qs[row][c4 + 2] = v.z; Qs[row][c4 + 3] = v.w;
    }

    float mrow[4], lrow[4], acc[4][4];
#pragma unroll
    for (int i = 0; i < 4; i++) {
        mrow[i] = -INFINITY;
        lrow[i] = 0.0f;
#pragma unroll
        for (int j = 0; j < 4; j++) acc[i][j] = 0.0f;
    }
    __syncthreads();

    for (int t = 0; t < 32; t++) {
        const int k0 = t * 64;
#pragma unroll
        for (int i = 0; i < 4; i++) {
            int f   = tid + i * 256;
            int row = f >> 4;
            int c4  = (f & 15) * 4;
            float4 kv4 = *reinterpret_cast<const float4*>(kb + (size_t)(k0 + row) * N1_ + c4);
            Ks[row][c4 + 0] = kv4.x; Ks[row][c4 + 1] = kv4.y;
            Ks[row][c4 + 2] = kv4.z; Ks[row][c4 + 3] = kv4.w;
            float4 vv4 = *reinterpret_cast<const float4*>(vb + (size_t)(k0 + row) * N1_ + c4);
            *reinterpret_cast<float4*>(&Vs[row][c4]) = vv4;
        }
        __syncthreads();

        float s[4][4];
#pragma unroll
        for (int i = 0; i < 4; i++)
#pragma unroll
            for (int j = 0; j < 4; j++) s[i][j] = 0.0f;

#pragma unroll
        for (int k = 0; k < 64; k++) {
            float qv[4], kv[4];
#pragma unroll
            for (int i = 0; i < 4; i++) qv[i] = Qs[tr * 4 + i][k];
#pragma unroll
            for (int j = 0; j < 4; j++) kv[j] = Ks[tc * 4 + j][k];
#pragma unroll
            for (int i = 0; i < 4; i++)
#pragma unroll
                for (int j = 0; j < 4; j++)
                    s[i][j] += qv[i] * kv[j];
        }

        float p[4][4], mnew[4], lsum[4];
#pragma unroll
        for (int i = 0; i < 4; i++) {
            const int4 mv = *reinterpret_cast<const int4*>(
                mb + (size_t)(tr * 4 + i) * L_ + k0 + tc * 4);
            float s0 = mv.x ? s[i][0] * 0.125f : 0.0f;
            float s1 = mv.y ? s[i][1] * 0.125f : 0.0f;
            float s2 = mv.z ? s[i][2] * 0.125f : 0.0f;
            float s3 = mv.w ? s[i][3] * 0.125f : 0.0f;

            float tm = fmaxf(fmaxf(s0, s1), fmaxf(s2, s3));
            tm = fmaxf(tm, __shfl_xor_sync(0xffffffffu, tm, 1));
            tm = fmaxf(tm, __shfl_xor_sync(0xffffffffu, tm, 2));
            tm = fmaxf(tm, __shfl_xor_sync(0xffffffffu, tm, 4));
            tm = fmaxf(tm, __shfl_xor_sync(0xffffffffu, tm, 8));
            mnew[i] = fmaxf(mrow[i], tm);

            float e0 = __expf(s0 - mnew[i]);
            float e1 = __expf(s1 - mnew[i]);
            float e2 = __expf(s2 - mnew[i]);
            float e3 = __expf(s3 - mnew[i]);
            float ls = e0 + e1 + e2 + e3;
            ls += __shfl_xor_sync(0xffffffffu, ls, 1);
            ls += __shfl_xor_sync(0xffffffffu, ls, 2);
            ls += __shfl_xor_sync(0xffffffffu, ls, 4);
            ls += __shfl_xor_sync(0xffffffffu, ls, 8);
            lsum[i] = ls;

            p[i][0] = mv.x ? e0 : 0.0f;
            p[i][1] = mv.y ? e1 : 0.0f;
            p[i][2] = mv.z ? e2 : 0.0f;
            p[i][3] = mv.w ? e3 : 0.0f;
        }

        __syncthreads();

#pragma unroll
        for (int i = 0; i < 4; i++)
#pragma unroll
            for (int j = 0; j < 4; j++)
                Ks[tr * 4 + i][tc * 4 + j] = p[i][j];

#pragma unroll
        for (int i = 0; i < 4; i++) {
            float sc = __expf(mrow[i] - mnew[i]);
            lrow[i] = lrow[i] * sc + lsum[i];
            mrow[i] = mnew[i];
#pragma unroll
            for (int j = 0; j < 4; j++) acc[i][j] *= sc;
        }
        __syncthreads();

#pragma unroll
        for (int k = 0; k < 64; k++) {
            float pv[4];
#pragma unroll
            for (int i = 0; i < 4; i++) pv[i] = Ks[tr * 4 + i][k];
            float4 vvf = *reinterpret_cast<const float4*>(&Vs[k][tc * 4]);
#pragma unroll
            for (int i = 0; i < 4; i++) {
                acc[i][0] += pv[i] * vvf.x;
                acc[i][1] += pv[i] * vvf.y;
                acc[i][2] += pv[i] * vvf.z;
                acc[i][3] += pv[i] * vvf.w;
            }
        }
        __syncthreads();
    }

    float* ob = ctx + ((size_t)(b * L_ + q0)) * D_ + h * DK_;
#pragma unroll
    for (int i = 0; i < 4; i++) {
        float inv = 1.0f / lrow[i];
        float4 o;
        o.x = acc[i][0] * inv;
        o.y = acc[i][1] * inv;
        o.z = acc[i][2] * inv;
        o.w = acc[i][3] * inv;
        *reinterpret_cast<float4*>(ob + (size_t)(tr * 4 + i) * D_ + tc * 4) = o;
    }
}

// ===========================================================================
// kernel_launch
// ===========================================================================
extern "C" void kernel_launch(void* const* d_in, const int* in_sizes, int n_in,
                              void* d_out, int out_size)
{
    const float* inputs = (const float*)d_in[0];
    const int*   mask   = (const int*)d_in[1];
    const float* W1     = (const float*)d_in[2];
    const float* b1     = (const float*)d_in[3];
    const float* W2     = (const float*)d_in[4];
    const float* b2     = (const float*)d_in[5];
    float* out = (float*)d_out;

    float* qkv = nullptr; float* ctx = nullptr;
    __nv_bfloat16* Abf = nullptr; __nv_bfloat16* Bbf = nullptr;
    cudaGetSymbolAddress((void**)&qkv, g_qkv);
    cudaGetSymbolAddress((void**)&ctx, g_ctx);
    cudaGetSymbolAddress((void**)&Abf, g_Abf);
    cudaGetSymbolAddress((void**)&Bbf, g_Bbf);

    const int attn_smem = (2 * 64 * 65 + 64 * 64) * (int)sizeof(float);
    cudaFuncSetAttribute(flash_attn_kernel,
                         cudaFuncAttributeMaxDynamicSharedMemorySize, attn_smem);

    // GEMM1: qkv = inputs @ W1 + b1   (split-bf16, K'=3072)
    pack_a_kernel<<<(M_ * D_ / 4) / 256, 256>>>(inputs, Abf);
    pack_bt_kernel<<<dim3(N1_ / 32, D_ / 32), dim3(32, 8)>>>(W1, Bbf, N1_);
    mma_gemm_kernel<<<dim3(N1_ / 128, M_ / 128), 256>>>(Abf, Bbf, b1, qkv, N1_);

    // Attention
    flash_attn_kernel<<<dim3(L_ / 64, B_ * H_), 256, attn_smem>>>(qkv, mask, ctx);

    // GEMM2: out = ctx @ W2 + b2
    pack_a_kernel<<<(M_ * D_ / 4) / 256, 256>>>(ctx, Abf);
    pack_bt_kernel<<<dim3(D_ / 32, D_ / 32), dim3(32, 8)>>>(W2, Bbf, D_);
    mma_gemm_kernel<<<dim3(D_ / 128, M_ / 128), 256>>>(Abf, Bbf, b2, out, D_);
}

// round 5
// speedup vs baseline: 2.0804x; 1.7345x over previous
#include <cuda_runtime.h>
#include <cuda_bf16.h>
#include <math.h>
#include <stdint.h>

// Problem constants
#define B_ 4
#define L_ 2048
#define D_ 1024
#define H_ 16
#define DK_ 64
#define M_ (B_ * L_)      // 8192
#define N1_ (3 * D_)      // 3072
#define K3_ 3072          // split-bf16 K' = 3*1024

// Scratch (device globals: allocation-free per harness rules)
__device__ float g_qkv[(size_t)M_ * N1_];            // 8192 x 3072 fp32
__device__ __nv_bfloat16 g_Abf[(size_t)M_ * K3_];    // 8192 x 3072 bf16 (A split)
__device__ __nv_bfloat16 g_Bbf[(size_t)N1_ * K3_];   // up to 3072 x 3072 bf16 (B^T split)

__device__ __forceinline__ uint32_t smem_u32(const void* p) {
    uint32_t a;
    asm("{ .reg .u64 t; cvta.to.shared.u64 t, %1; cvt.u32.u64 %0, t; }" : "=r"(a) : "l"(p));
    return a;
}
#define LDMATRIX_X4(r0, r1, r2, r3, addr) \
    asm volatile("ldmatrix.sync.aligned.m8n8.x4.shared.b16 {%0,%1,%2,%3}, [%4];" \
                 : "=r"(r0), "=r"(r1), "=r"(r2), "=r"(r3) : "r"(addr))
#define MMA_BF16(d, a, b0, b1) \
    asm volatile("mma.sync.aligned.m16n8k16.row.col.f32.bf16.bf16.f32 " \
                 "{%0,%1,%2,%3}, {%4,%5,%6,%7}, {%8,%9}, {%0,%1,%2,%3};" \
                 : "+f"((d)[0]), "+f"((d)[1]), "+f"((d)[2]), "+f"((d)[3]) \
                 : "r"((a)[0]), "r"((a)[1]), "r"((a)[2]), "r"((a)[3]), \
                   "r"(b0), "r"(b1))

__device__ __forceinline__ void pack_hilo(float a, float b, uint32_t& hi, uint32_t& lo) {
    __nv_bfloat162 h, l;
    h.x = __float2bfloat16(a); h.y = __float2bfloat16(b);
    l.x = __float2bfloat16(a - __bfloat162float(h.x));
    l.y = __float2bfloat16(b - __bfloat162float(h.y));
    hi = *reinterpret_cast<uint32_t*>(&h);
    lo = *reinterpret_cast<uint32_t*>(&l);
}

// ===========================================================================
// Split-bf16 pack kernels
//   A'[m] = [hi(k) | lo(k) | hi(k)]  (K=1024 -> K'=3072)
//   B'^T[n] = [hi(k) | hi(k) | lo(k)]
// ===========================================================================
__global__ __launch_bounds__(256) void pack_a_kernel(
    const float* __restrict__ X, __nv_bfloat16* __restrict__ A2)
{
    int i = (blockIdx.x * 256 + threadIdx.x) * 4;     // over M_*1024 elements
    int m = i >> 10;
    int k = i & 1023;
    float4 v = *reinterpret_cast<const float4*>(X + i);

    __nv_bfloat16 h0 = __float2bfloat16(v.x), h1 = __float2bfloat16(v.y);
    __nv_bfloat16 h2 = __float2bfloat16(v.z), h3 = __float2bfloat16(v.w);
    __nv_bfloat16 l0 = __float2bfloat16(v.x - __bfloat162float(h0));
    __nv_bfloat16 l1 = __float2bfloat16(v.y - __bfloat162float(h1));
    __nv_bfloat16 l2 = __float2bfloat16(v.z - __bfloat162float(h2));
    __nv_bfloat16 l3 = __float2bfloat16(v.w - __bfloat162float(h3));

    size_t ro = (size_t)m * K3_;
    __nv_bfloat162 hA; hA.x = h0; hA.y = h1;
    __nv_bfloat162 hB; hB.x = h2; hB.y = h3;
    __nv_bfloat162 lA; lA.x = l0; lA.y = l1;
    __nv_bfloat162 lB; lB.x = l2; lB.y = l3;

    __nv_bfloat162* p0 = reinterpret_cast<__nv_bfloat162*>(A2 + ro + k);
    p0[0] = hA; p0[1] = hB;
    __nv_bfloat162* p1 = reinterpret_cast<__nv_bfloat162*>(A2 + ro + 1024 + k);
    p1[0] = lA; p1[1] = lB;
    __nv_bfloat162* p2 = reinterpret_cast<__nv_bfloat162*>(A2 + ro + 2048 + k);
    p2[0] = hA; p2[1] = hB;
}

// W (K x N) fp32 -> Bt (N x K3_) bf16 with [hi, hi, lo] segments (K=1024)
__global__ void pack_bt_kernel(
    const float* __restrict__ W, __nv_bfloat16* __restrict__ Bt, int N)
{
    __shared__ float ts[32][33];
    int n0 = blockIdx.x * 32, k0 = blockIdx.y * 32;
    int tx = threadIdx.x, ty = threadIdx.y;   // (32, 8)
#pragma unroll
    for (int r = 0; r < 32; r += 8)
        ts[ty + r][tx] = W[(size_t)(k0 + ty + r) * N + n0 + tx];
    __syncthreads();
#pragma unroll
    for (int r = 0; r < 32; r += 8) {
        int n = n0 + ty + r;
        int k = k0 + tx;
        float x = ts[tx][ty + r];
        __nv_bfloat16 hi = __float2bfloat16(x);
        __nv_bfloat16 lo = __float2bfloat16(x - __bfloat162float(hi));
        size_t ro = (size_t)n * K3_;
        Bt[ro + k]        = hi;
        Bt[ro + 1024 + k] = hi;
        Bt[ro + 2048 + k] = lo;
    }
}

// ===========================================================================
// HMMA GEMM (proven R3):  C = A2 @ Bt^T + bias
// CTA tile 128x128, BK=32, double-buffered smem, 8 warps (4m x 2n).
// ===========================================================================
__global__ __launch_bounds__(256) void mma_gemm_kernel(
    const __nv_bfloat16* __restrict__ A2,
    const __nv_bfloat16* __restrict__ Bt,
    const float* __restrict__ bias,
    float* __restrict__ C, int N)
{
    __shared__ __nv_bfloat16 As[2][128][40];
    __shared__ __nv_bfloat16 Bs[2][128][40];

    const int tid  = threadIdx.x;
    const int lane = tid & 31;
    const int wid  = tid >> 5;
    const int wm   = wid & 3;
    const int wn   = wid >> 2;
    const int bm = blockIdx.y, bn = blockIdx.x;

    const __nv_bfloat16* Ag = A2 + (size_t)(bm * 128) * K3_;
    const __nv_bfloat16* Bg = Bt + (size_t)(bn * 128) * K3_;

    const uint32_t aBase = smem_u32(&As[0][0][0]);
    const uint32_t bBase = smem_u32(&Bs[0][0][0]);
    const uint32_t BUFB = 128 * 40 * 2;

    const uint32_t aRowOff = (uint32_t)(wm * 32 + (lane & 15)) * 80 + (uint32_t)(lane >> 4) * 16;
    const uint32_t bRowOff0 = (uint32_t)(wn * 64 + ((lane >> 3) * 8) + (lane & 7)) * 80;

    float acc[2][8][4];
#pragma unroll
    for (int i = 0; i < 2; i++)
#pragma unroll
        for (int j = 0; j < 8; j++)
#pragma unroll
            for (int q = 0; q < 4; q++) acc[i][j][q] = 0.0f;

    const int NC = K3_ / 32;

    uint4 ra[2], rb[2];
    const int r0 = tid >> 2, s0 = (tid & 3) * 8;
    const int r1 = (tid + 256) >> 2, s1 = ((tid + 256) & 3) * 8;

    auto LDG = [&](int c) {
        ra[0] = *reinterpret_cast<const uint4*>(Ag + (size_t)r0 * K3_ + c * 32 + s0);
        ra[1] = *reinterpret_cast<const uint4*>(Ag + (size_t)r1 * K3_ + c * 32 + s1);
        rb[0] = *reinterpret_cast<const uint4*>(Bg + (size_t)r0 * K3_ + c * 32 + s0);
        rb[1] = *reinterpret_cast<const uint4*>(Bg + (size_t)r1 * K3_ + c * 32 + s1);
    };
    auto STS = [&](int buf) {
        *reinterpret_cast<uint4*>(&As[buf][r0][s0]) = ra[0];
        *reinterpret_cast<uint4*>(&As[buf][r1][s1]) = ra[1];
        *reinterpret_cast<uint4*>(&Bs[buf][r0][s0]) = rb[0];
        *reinterpret_cast<uint4*>(&Bs[buf][r1][s1]) = rb[1];
    };

    LDG(0);
    STS(0);
    __syncthreads();

    for (int c = 0; c < NC; c++) {
        if (c + 1 < NC) LDG(c + 1);
        const int buf = c & 1;
        const uint32_t aB = aBase + buf * BUFB;
        const uint32_t bB = bBase + buf * BUFB;

#pragma unroll
        for (int s = 0; s < 2; s++) {
            uint32_t aF[2][4];
#pragma unroll
            for (int mi = 0; mi < 2; mi++) {
                uint32_t addr = aB + aRowOff + (uint32_t)(mi * 16) * 80 + s * 32;
                LDMATRIX_X4(aF[mi][0], aF[mi][1], aF[mi][2], aF[mi][3], addr);
            }
            uint32_t bF0[8], bF1[8];
#pragma unroll
            for (int g = 0; g < 2; g++) {
                uint32_t addr = bB + bRowOff0 + (uint32_t)(g * 32) * 80 + s * 32;
                LDMATRIX_X4(bF0[g*4+0], bF0[g*4+1], bF0[g*4+2], bF0[g*4+3], addr);
                LDMATRIX_X4(bF1[g*4+0], bF1[g*4+1], bF1[g*4+2], bF1[g*4+3], addr + 16);
            }
#pragma unroll
            for (int mi = 0; mi < 2; mi++)
#pragma unroll
                for (int nj = 0; nj < 8; nj++)
                    MMA_BF16(acc[mi][nj], aF[mi], bF0[nj], bF1[nj]);
        }

        __syncthreads();
        if (c + 1 < NC) {
            STS((c + 1) & 1);
            __syncthreads();
        }
    }

    const int qr = lane >> 2;
    const int qc = (lane & 3) * 2;
#pragma unroll
    for (int mi = 0; mi < 2; mi++) {
        int row = bm * 128 + wm * 32 + mi * 16 + qr;
#pragma unroll
        for (int nj = 0; nj < 8; nj++) {
            int col = bn * 128 + wn * 64 + nj * 8 + qc;
            float bv0 = __ldg(bias + col);
            float bv1 = __ldg(bias + col + 1);
            float2 o0, o1;
            o0.x = acc[mi][nj][0] + bv0;
            o0.y = acc[mi][nj][1] + bv1;
            o1.x = acc[mi][nj][2] + bv0;
            o1.y = acc[mi][nj][3] + bv1;
            *reinterpret_cast<float2*>(C + (size_t)row * N + col) = o0;
            *reinterpret_cast<float2*>(C + (size_t)(row + 8) * N + col) = o1;
        }
    }
}

// ===========================================================================
// Tensor-core flash attention (split-bf16 QK^T and P.V)
// CTA: 128 q-rows x one (b,h). 8 warps, warp owns 16 q-rows (full rows).
// Key tiles of 64. Output written directly as split-bf16 A' for GEMM2.
// Smem (bf16 elems, stride 72/row): Qhi Qlo [128x72]; Khi Klo Vthi Vtlo [64x72]
// ===========================================================================
#define AQHI 0
#define AQLO (128*72)
#define AKHI (2*128*72)
#define AKLO (AKHI + 64*72)
#define AVHI (AKLO + 64*72)
#define AVLO (AVHI + 64*72)
#define ATT_SMEM ((AVLO + 64*72) * 2)   // bytes = 73728

__global__ __launch_bounds__(256) void flash_attn_mma_kernel(
    const float* __restrict__ qkv,
    const int*   __restrict__ mask,
    __nv_bfloat16* __restrict__ Abf)
{
    extern __shared__ __nv_bfloat16 sm[];
    const int tid  = threadIdx.x;
    const int lane = tid & 31;
    const int w    = tid >> 5;
    const int bh = blockIdx.y, b = bh >> 4, h = bh & 15;
    const int q0 = blockIdx.x * 128;

    const float* qb = qkv + (size_t)(b * L_ + q0) * N1_ + h * DK_;
    const float* kb = qkv + (size_t)(b * L_) * N1_ + D_     + h * DK_;
    const float* vb = qkv + (size_t)(b * L_) * N1_ + 2 * D_ + h * DK_;

    // ---- Load Q tile (128x64 fp32) -> Qhi/Qlo smem
#pragma unroll
    for (int i = 0; i < 8; i++) {
        int idx = tid + i * 256;
        int row = idx >> 4, c4 = (idx & 15) * 4;
        float4 v = *reinterpret_cast<const float4*>(qb + (size_t)row * N1_ + c4);
        uint32_t h0, l0, h1, l1;
        pack_hilo(v.x, v.y, h0, l0);
        pack_hilo(v.z, v.w, h1, l1);
        uint32_t* qh = reinterpret_cast<uint32_t*>(sm + AQHI + row * 72 + c4);
        uint32_t* ql = reinterpret_cast<uint32_t*>(sm + AQLO + row * 72 + c4);
        qh[0] = h0; qh[1] = h1;
        ql[0] = l0; ql[1] = l1;
    }

    const uint32_t smB = smem_u32(sm);
    const uint32_t QHI2 = smB;
    const uint32_t QLO2 = smB + AQLO * 2;
    const uint32_t KHI2 = smB + AKHI * 2;
    const uint32_t KLO2 = smB + AKLO * 2;
    const uint32_t VHI2 = smB + AVHI * 2;
    const uint32_t VLO2 = smB + AVLO * 2;

    // ldmatrix lane addressing
    const uint32_t qRowByte = (uint32_t)(16 * w + (lane & 15)) * 144 + (uint32_t)(lane >> 4) * 16;
    const uint32_t bLaneByte = (uint32_t)lane * 144;   // rows 0..31 per x4 group

    // K/V prefetch regs (tile t): 4 float4 each
    float4 kreg[4], vreg[4];
    auto LDGKV = [&](int t) {
        int k0 = t * 64;
#pragma unroll
        for (int i = 0; i < 4; i++) {
            int idx = tid + i * 256;
            int row = idx >> 4, c4 = (idx & 15) * 4;
            kreg[i] = *reinterpret_cast<const float4*>(kb + (size_t)(k0 + row) * N1_ + c4);
            vreg[i] = *reinterpret_cast<const float4*>(vb + (size_t)(k0 + row) * N1_ + c4);
        }
    };
    auto STSKV = [&]() {
#pragma unroll
        for (int i = 0; i < 4; i++) {
            int idx = tid + i * 256;
            int row = idx >> 4, c4 = (idx & 15) * 4;
            uint32_t h0, l0, h1, l1;
            pack_hilo(kreg[i].x, kreg[i].y, h0, l0);
            pack_hilo(kreg[i].z, kreg[i].w, h1, l1);
            uint32_t* kh = reinterpret_cast<uint32_t*>(sm + AKHI + row * 72 + c4);
            uint32_t* kl = reinterpret_cast<uint32_t*>(sm + AKLO + row * 72 + c4);
            kh[0] = h0; kh[1] = h1;
            kl[0] = l0; kl[1] = l1;
            // V transposed: Vt[d][k]
            float vv[4] = {vreg[i].x, vreg[i].y, vreg[i].z, vreg[i].w};
#pragma unroll
            for (int q = 0; q < 4; q++) {
                __nv_bfloat16 hv = __float2bfloat16(vv[q]);
                __nv_bfloat16 lv = __float2bfloat16(vv[q] - __bfloat162float(hv));
                sm[AVHI + (c4 + q) * 72 + row] = hv;
                sm[AVLO + (c4 + q) * 72 + row] = lv;
            }
        }
    };

    // per-thread softmax state: rows g = lane>>2 (and +8) within warp's 16 rows
    const int g  = lane >> 2;
    const int t4 = lane & 3;
    float m0 = -INFINITY, m1 = -INFINITY;
    float lr0 = 0.0f, lr1 = 0.0f;
    float oAcc[8][4];
#pragma unroll
    for (int j = 0; j < 8; j++)
#pragma unroll
        for (int q = 0; q < 4; q++) oAcc[j][q] = 0.0f;

    const int* mbase0 = mask + (size_t)b * L_ * L_ + (size_t)(q0 + 16 * w + g) * L_ + 2 * t4;
    const int* mbase1 = mbase0 + 8 * L_;

    LDGKV(0);
    __syncthreads();   // Q smem ready

    for (int t = 0; t < 32; t++) {
        STSKV();
        __syncthreads();
        if (t + 1 < 32) LDGKV(t + 1);

        // ---- S = Q' K'^T  (3 split groups: Qhi.Khi + Qlo.Khi + Qhi.Klo)
        float sAcc[8][4];
#pragma unroll
        for (int j = 0; j < 8; j++)
#pragma unroll
            for (int q = 0; q < 4; q++) sAcc[j][q] = 0.0f;

#pragma unroll
        for (int s = 0; s < 4; s++) {
            uint32_t aH[4], aL[4];
            LDMATRIX_X4(aH[0], aH[1], aH[2], aH[3], QHI2 + qRowByte + s * 32);
            LDMATRIX_X4(aL[0], aL[1], aL[2], aL[3], QLO2 + qRowByte + s * 32);
            uint32_t k0h[8], k1h[8], k0l[8], k1l[8];
#pragma unroll
            for (int gg = 0; gg < 2; gg++) {
                uint32_t base = bLaneByte + gg * 4608 + s * 32;
                LDMATRIX_X4(k0h[gg*4+0], k0h[gg*4+1], k0h[gg*4+2], k0h[gg*4+3], KHI2 + base);
                LDMATRIX_X4(k1h[gg*4+0], k1h[gg*4+1], k1h[gg*4+2], k1h[gg*4+3], KHI2 + base + 16);
                LDMATRIX_X4(k0l[gg*4+0], k0l[gg*4+1], k0l[gg*4+2], k0l[gg*4+3], KLO2 + base);
                LDMATRIX_X4(k1l[gg*4+0], k1l[gg*4+1], k1l[gg*4+2], k1l[gg*4+3], KLO2 + base + 16);
            }
#pragma unroll
            for (int j = 0; j < 8; j++) {
                MMA_BF16(sAcc[j], aH, k0h[j], k1h[j]);
                MMA_BF16(sAcc[j], aL, k0h[j], k1h[j]);
                MMA_BF16(sAcc[j], aH, k0l[j], k1l[j]);
            }
        }

        // ---- mask + scale + online softmax
        const int k0 = t * 64;
        uint32_t mbits = 0;
        float mx0 = -INFINITY, mx1 = -INFINITY;
#pragma unroll
        for (int j = 0; j < 8; j++) {
            int2 mv0 = *reinterpret_cast<const int2*>(mbase0 + k0 + 8 * j);
            int2 mv1 = *reinterpret_cast<const int2*>(mbase1 + k0 + 8 * j);
            float v0 = mv0.x ? sAcc[j][0] * 0.125f : 0.0f;
            float v1 = mv0.y ? sAcc[j][1] * 0.125f : 0.0f;
            float v2 = mv1.x ? sAcc[j][2] * 0.125f : 0.0f;
            float v3 = mv1.y ? sAcc[j][3] * 0.125f : 0.0f;
            sAcc[j][0] = v0; sAcc[j][1] = v1; sAcc[j][2] = v2; sAcc[j][3] = v3;
            mbits |= (mv0.x ? 1u : 0u) << (4 * j)
                  |  (mv0.y ? 1u : 0u) << (4 * j + 1)
                  |  (mv1.x ? 1u : 0u) << (4 * j + 2)
                  |  (mv1.y ? 1u : 0u) << (4 * j + 3);
            mx0 = fmaxf(mx0, fmaxf(v0, v1));
            mx1 = fmaxf(mx1, fmaxf(v2, v3));
        }
        mx0 = fmaxf(mx0, __shfl_xor_sync(0xffffffffu, mx0, 1));
        mx0 = fmaxf(mx0, __shfl_xor_sync(0xffffffffu, mx0, 2));
        mx1 = fmaxf(mx1, __shfl_xor_sync(0xffffffffu, mx1, 1));
        mx1 = fmaxf(mx1, __shfl_xor_sync(0xffffffffu, mx1, 2));
        float mn0 = fmaxf(m0, mx0), mn1 = fmaxf(m1, mx1);

        float ls0 = 0.0f, ls1 = 0.0f;
#pragma unroll
        for (int j = 0; j < 8; j++) {
            float e0 = __expf(sAcc[j][0] - mn0);
            float e1 = __expf(sAcc[j][1] - mn0);
            float e2 = __expf(sAcc[j][2] - mn1);
            float e3 = __expf(sAcc[j][3] - mn1);
            ls0 += e0 + e1;
            ls1 += e2 + e3;
            sAcc[j][0] = ((mbits >> (4 * j))     & 1u) ? e0 : 0.0f;
            sAcc[j][1] = ((mbits >> (4 * j + 1)) & 1u) ? e1 : 0.0f;
            sAcc[j][2] = ((mbits >> (4 * j + 2)) & 1u) ? e2 : 0.0f;
            sAcc[j][3] = ((mbits >> (4 * j + 3)) & 1u) ? e3 : 0.0f;
        }
        ls0 += __shfl_xor_sync(0xffffffffu, ls0, 1);
        ls0 += __shfl_xor_sync(0xffffffffu, ls0, 2);
        ls1 += __shfl_xor_sync(0xffffffffu, ls1, 1);
        ls1 += __shfl_xor_sync(0xffffffffu, ls1, 2);

        float sc0 = __expf(m0 - mn0), sc1 = __expf(m1 - mn1);
        lr0 = lr0 * sc0 + ls0;
        lr1 = lr1 * sc1 + ls1;
        m0 = mn0; m1 = mn1;
#pragma unroll
        for (int j = 0; j < 8; j++) {
            oAcc[j][0] *= sc0; oAcc[j][1] *= sc0;
            oAcc[j][2] *= sc1; oAcc[j][3] *= sc1;
        }

        // ---- O += P' Vt'  (P fragments from registers, 3 split groups)
#pragma unroll
        for (int s = 0; s < 4; s++) {
            uint32_t pH[4], pL[4];
            pack_hilo(sAcc[2*s][0],   sAcc[2*s][1],   pH[0], pL[0]);
            pack_hilo(sAcc[2*s][2],   sAcc[2*s][3],   pH[1], pL[1]);
            pack_hilo(sAcc[2*s+1][0], sAcc[2*s+1][1], pH[2], pL[2]);
            pack_hilo(sAcc[2*s+1][2], sAcc[2*s+1][3], pH[3], pL[3]);
            uint32_t v0h[8], v1h[8], v0l[8], v1l[8];
#pragma unroll
            for (int gg = 0; gg < 2; gg++) {
                uint32_t base = bLaneByte + gg * 4608 + s * 32;
                LDMATRIX_X4(v0h[gg*4+0], v0h[gg*4+1], v0h[gg*4+2], v0h[gg*4+3], VHI2 + base);
                LDMATRIX_X4(v1h[gg*4+0], v1h[gg*4+1], v1h[gg*4+2], v1h[gg*4+3], VHI2 + base + 16);
                LDMATRIX_X4(v0l[gg*4+0], v0l[gg*4+1], v0l[gg*4+2], v0l[gg*4+3], VLO2 + base);
                LDMATRIX_X4(v1l[gg*4+0], v1l[gg*4+1], v1l[gg*4+2], v1l[gg*4+3], VLO2 + base + 16);
            }
#pragma unroll
            for (int j = 0; j < 8; j++) {
                MMA_BF16(oAcc[j], pH, v0h[j], v1h[j]);
                MMA_BF16(oAcc[j], pL, v0h[j], v1h[j]);
                MMA_BF16(oAcc[j], pH, v0l[j], v1l[j]);
            }
        }
        __syncthreads();   // done reading K/V tile t
    }

    // ---- Epilogue: normalize, write split-bf16 A' rows for GEMM2
    float i0 = 1.0f / lr0, i1 = 1.0f / lr1;
    __nv_bfloat16* ar0 = Abf + (size_t)(b * L_ + q0 + 16 * w + g) * K3_ + h * DK_ + 2 * t4;
    __nv_bfloat16* ar1 = ar0 + (size_t)8 * K3_;
#pragma unroll
    for (int j = 0; j < 8; j++) {
        uint32_t h0, l0, h1, l1;
        pack_hilo(oAcc[j][0] * i0, oAcc[j][1] * i0, h0, l0);
        pack_hilo(oAcc[j][2] * i1, oAcc[j][3] * i1, h1, l1);
        int c = 8 * j;
        *reinterpret_cast<uint32_t*>(ar0 + c)        = h0;
        *reinterpret_cast<uint32_t*>(ar0 + 1024 + c) = l0;
        *reinterpret_cast<uint32_t*>(ar0 + 2048 + c) = h0;
        *reinterpret_cast<uint32_t*>(ar1 + c)        = h1;
        *reinterpret_cast<uint32_t*>(ar1 + 1024 + c) = l1;
        *reinterpret_cast<uint32_t*>(ar1 + 2048 + c) = h1;
    }
}

// ===========================================================================
// kernel_launch
// ===========================================================================
extern "C" void kernel_launch(void* const* d_in, const int* in_sizes, int n_in,
                              void* d_out, int out_size)
{
    const float* inputs = (const float*)d_in[0];
    const int*   mask   = (const int*)d_in[1];
    const float* W1     = (const float*)d_in[2];
    const float* b1     = (const float*)d_in[3];
    const float* W2     = (const float*)d_in[4];
    const float* b2     = (const float*)d_in[5];
    float* out = (float*)d_out;

    float* qkv = nullptr;
    __nv_bfloat16* Abf = nullptr; __nv_bfloat16* Bbf = nullptr;
    cudaGetSymbolAddress((void**)&qkv, g_qkv);
    cudaGetSymbolAddress((void**)&Abf, g_Abf);
    cudaGetSymbolAddress((void**)&Bbf, g_Bbf);

    cudaFuncSetAttribute(flash_attn_mma_kernel,
                         cudaFuncAttributeMaxDynamicSharedMemorySize, ATT_SMEM);

    // GEMM1: qkv = inputs @ W1 + b1   (split-bf16, K'=3072)
    pack_a_kernel<<<(M_ * D_ / 4) / 256, 256>>>(inputs, Abf);
    pack_bt_kernel<<<dim3(N1_ / 32, D_ / 32), dim3(32, 8)>>>(W1, Bbf, N1_);
    mma_gemm_kernel<<<dim3(N1_ / 128, M_ / 128), 256>>>(Abf, Bbf, b1, qkv, N1_);

    // Attention (tensor-core); writes split-bf16 A' for GEMM2 directly
    flash_attn_mma_kernel<<<dim3(L_ / 128, B_ * H_), 256, ATT_SMEM>>>(qkv, mask, Abf);

    // GEMM2: out = ctx @ W2 + b2
    pack_bt_kernel<<<dim3(D_ / 32, D_ / 32), dim3(32, 8)>>>(W2, Bbf, D_);
    mma_gemm_kernel<<<dim3(D_ / 128, M_ / 128), 256>>>(Abf, Bbf, b2, out, D_);
}

// round 7
// speedup vs baseline: 2.5873x; 1.2436x over previous
#include <cuda_runtime.h>
#include <cuda_bf16.h>
#include <math.h>
#include <stdint.h>

// Problem constants
#define B_ 4
#define L_ 2048
#define D_ 1024
#define H_ 16
#define DK_ 64
#define M_ (B_ * L_)      // 8192
#define N1_ (3 * D_)      // 3072
#define K3_ 3072          // split-bf16 K' = 3*1024

// Scratch (device globals: allocation-free per harness rules)
__device__ float g_qkv[(size_t)M_ * N1_];            // 8192 x 3072 fp32
__device__ __nv_bfloat16 g_Abf[(size_t)M_ * K3_];    // 8192 x 3072 bf16 (A split)
__device__ __nv_bfloat16 g_Bbf[(size_t)N1_ * K3_];   // up to 3072 x 3072 bf16 (B^T split)

__device__ __forceinline__ uint32_t smem_u32(const void* p) {
    uint32_t a;
    asm("{ .reg .u64 t; cvta.to.shared.u64 t, %1; cvt.u32.u64 %0, t; }" : "=r"(a) : "l"(p));
    return a;
}
#define LDMATRIX_X4(r0, r1, r2, r3, addr) \
    asm volatile("ldmatrix.sync.aligned.m8n8.x4.shared.b16 {%0,%1,%2,%3}, [%4];" \
                 : "=r"(r0), "=r"(r1), "=r"(r2), "=r"(r3) : "r"(addr))
#define LDMATRIX_X4_T(r0, r1, r2, r3, addr) \
    asm volatile("ldmatrix.sync.aligned.m8n8.x4.trans.shared.b16 {%0,%1,%2,%3}, [%4];" \
                 : "=r"(r0), "=r"(r1), "=r"(r2), "=r"(r3) : "r"(addr))
#define MMA_BF16(d, a, b0, b1) \
    asm volatile("mma.sync.aligned.m16n8k16.row.col.f32.bf16.bf16.f32 " \
                 "{%0,%1,%2,%3}, {%4,%5,%6,%7}, {%8,%9}, {%0,%1,%2,%3};" \
                 : "+f"((d)[0]), "+f"((d)[1]), "+f"((d)[2]), "+f"((d)[3]) \
                 : "r"((a)[0]), "r"((a)[1]), "r"((a)[2]), "r"((a)[3]), \
                   "r"(b0), "r"(b1))
#define CP_ASYNC16(dst, src) \
    asm volatile("cp.async.cg.shared.global [%0], [%1], 16;" :: "r"(dst), "l"(src))
#define CP_COMMIT() asm volatile("cp.async.commit_group;")
#define CP_WAIT1()  asm volatile("cp.async.wait_group 1;")
#define CP_WAIT0()  asm volatile("cp.async.wait_group 0;")

__device__ __forceinline__ void pack_hilo(float a, float b, uint32_t& hi, uint32_t& lo) {
    __nv_bfloat162 h, l;
    h.x = __float2bfloat16(a); h.y = __float2bfloat16(b);
    l.x = __float2bfloat16(a - __bfloat162float(h.x));
    l.y = __float2bfloat16(b - __bfloat162float(h.y));
    hi = *reinterpret_cast<uint32_t*>(&h);
    lo = *reinterpret_cast<uint32_t*>(&l);
}

// ===========================================================================
// Split-bf16 pack kernels
// ===========================================================================
__global__ __launch_bounds__(256) void pack_a_kernel(
    const float* __restrict__ X, __nv_bfloat16* __restrict__ A2)
{
    int i = (blockIdx.x * 256 + threadIdx.x) * 4;
    int m = i >> 10;
    int k = i & 1023;
    float4 v = *reinterpret_cast<const float4*>(X + i);

    uint32_t hA, lA, hB, lB;
    pack_hilo(v.x, v.y, hA, lA);
    pack_hilo(v.z, v.w, hB, lB);

    size_t ro = (size_t)m * K3_;
    uint32_t* p0 = reinterpret_cast<uint32_t*>(A2 + ro + k);
    p0[0] = hA; p0[1] = hB;
    uint32_t* p1 = reinterpret_cast<uint32_t*>(A2 + ro + 1024 + k);
    p1[0] = lA; p1[1] = lB;
    uint32_t* p2 = reinterpret_cast<uint32_t*>(A2 + ro + 2048 + k);
    p2[0] = hA; p2[1] = hB;
}

// W (K x N) fp32 -> Bt (N x K3_) bf16 with [hi, hi, lo] segments (K=1024)
__global__ void pack_bt_kernel(
    const float* __restrict__ W, __nv_bfloat16* __restrict__ Bt, int N)
{
    __shared__ float ts[32][33];
    int n0 = blockIdx.x * 32, k0 = blockIdx.y * 32;
    int tx = threadIdx.x, ty = threadIdx.y;   // (32, 8)
#pragma unroll
    for (int r = 0; r < 32; r += 8)
        ts[ty + r][tx] = W[(size_t)(k0 + ty + r) * N + n0 + tx];
    __syncthreads();
#pragma unroll
    for (int r = 0; r < 32; r += 8) {
        int n = n0 + ty + r;
        int k = k0 + tx;
        float x = ts[tx][ty + r];
        __nv_bfloat16 hi = __float2bfloat16(x);
        __nv_bfloat16 lo = __float2bfloat16(x - __bfloat162float(hi));
        size_t ro = (size_t)n * K3_;
        Bt[ro + k]        = hi;
        Bt[ro + 1024 + k] = hi;
        Bt[ro + 2048 + k] = lo;
    }
}

// ===========================================================================
// HMMA GEMM with 3-stage cp.async pipeline:  C = A2 @ Bt^T + bias
// CTA tile 128x128, BK=32, 8 warps (4m x 2n). Dynamic smem: 61440 B.
// ===========================================================================
#define G_STAGE_ELEMS (128 * 40)           // per operand per stage
#define G_SMEM_BYTES  (6 * G_STAGE_ELEMS * 2)

__global__ __launch_bounds__(256) void mma_gemm_kernel(
    const __nv_bfloat16* __restrict__ A2,
    const __nv_bfloat16* __restrict__ Bt,
    const float* __restrict__ bias,
    float* __restrict__ C, int N)
{
    extern __shared__ __nv_bfloat16 gsm[];
    const int tid  = threadIdx.x;
    const int lane = tid & 31;
    const int wid  = tid >> 5;
    const int wm   = wid & 3;
    const int wn   = wid >> 2;
    const int bm = blockIdx.y, bn = blockIdx.x;

    const __nv_bfloat16* Ag = A2 + (size_t)(bm * 128) * K3_;
    const __nv_bfloat16* Bg = Bt + (size_t)(bn * 128) * K3_;

    const uint32_t aBase0 = smem_u32(gsm);
    const uint32_t bBase0 = aBase0 + 3 * G_STAGE_ELEMS * 2;

    const uint32_t aRowOff = (uint32_t)(wm * 32 + (lane & 15)) * 80 + (uint32_t)(lane >> 4) * 16;
    const uint32_t bRowOff0 = (uint32_t)(wn * 64 + ((lane >> 3) * 8) + (lane & 7)) * 80;

    const int r0 = tid >> 2, s0 = (tid & 3) * 8;
    const int r1 = 64 + (tid >> 2), s1 = (tid & 3) * 8;
    const uint32_t aSt0 = (uint32_t)(r0 * 40 + s0) * 2;
    const uint32_t aSt1 = (uint32_t)(r1 * 40 + s1) * 2;

    auto ISSUE = [&](int c, int st) {
        uint32_t ab = aBase0 + st * (G_STAGE_ELEMS * 2);
        uint32_t bb = bBase0 + st * (G_STAGE_ELEMS * 2);
        CP_ASYNC16(ab + aSt0, Ag + (size_t)r0 * K3_ + c * 32 + s0);
        CP_ASYNC16(ab + aSt1, Ag + (size_t)r1 * K3_ + c * 32 + s1);
        CP_ASYNC16(bb + aSt0, Bg + (size_t)r0 * K3_ + c * 32 + s0);
        CP_ASYNC16(bb + aSt1, Bg + (size_t)r1 * K3_ + c * 32 + s1);
        CP_COMMIT();
    };

    float acc[2][8][4];
#pragma unroll
    for (int i = 0; i < 2; i++)
#pragma unroll
        for (int j = 0; j < 8; j++)
#pragma unroll
            for (int q = 0; q < 4; q++) acc[i][j][q] = 0.0f;

    const int NC = K3_ / 32;   // 96

    ISSUE(0, 0);
    ISSUE(1, 1);

    for (int c = 0; c < NC; c++) {
        const int st = c % 3;
        // Pipeline-full: 2 groups pending -> wait_group 1 leaves newest in flight.
        // Drain (last 2 iterations): must wait for everything.
        if (c + 2 < NC) { CP_WAIT1(); } else { CP_WAIT0(); }
        __syncthreads();

        const uint32_t aB = aBase0 + st * (G_STAGE_ELEMS * 2);
        const uint32_t bB = bBase0 + st * (G_STAGE_ELEMS * 2);
#pragma unroll
        for (int s = 0; s < 2; s++) {
            uint32_t aF[2][4];
#pragma unroll
            for (int mi = 0; mi < 2; mi++) {
                uint32_t addr = aB + aRowOff + (uint32_t)(mi * 16) * 80 + s * 32;
                LDMATRIX_X4(aF[mi][0], aF[mi][1], aF[mi][2], aF[mi][3], addr);
            }
            uint32_t bF0[8], bF1[8];
#pragma unroll
            for (int g = 0; g < 2; g++) {
                uint32_t addr = bB + bRowOff0 + (uint32_t)(g * 32) * 80 + s * 32;
                LDMATRIX_X4(bF0[g*4+0], bF0[g*4+1], bF0[g*4+2], bF0[g*4+3], addr);
                LDMATRIX_X4(bF1[g*4+0], bF1[g*4+1], bF1[g*4+2], bF1[g*4+3], addr + 16);
            }
#pragma unroll
            for (int mi = 0; mi < 2; mi++)
#pragma unroll
                for (int nj = 0; nj < 8; nj++)
                    MMA_BF16(acc[mi][nj], aF[mi], bF0[nj], bF1[nj]);
        }

        if (c + 2 < NC) ISSUE(c + 2, (c + 2) % 3);
    }

    const int qr = lane >> 2;
    const int qc = (lane & 3) * 2;
#pragma unroll
    for (int mi = 0; mi < 2; mi++) {
        int row = bm * 128 + wm * 32 + mi * 16 + qr;
#pragma unroll
        for (int nj = 0; nj < 8; nj++) {
            int col = bn * 128 + wn * 64 + nj * 8 + qc;
            float bv0 = __ldg(bias + col);
            float bv1 = __ldg(bias + col + 1);
            float2 o0, o1;
            o0.x = acc[mi][nj][0] + bv0;
            o0.y = acc[mi][nj][1] + bv1;
            o1.x = acc[mi][nj][2] + bv0;
            o1.y = acc[mi][nj][3] + bv1;
            *reinterpret_cast<float2*>(C + (size_t)row * N + col) = o0;
            *reinterpret_cast<float2*>(C + (size_t)(row + 8) * N + col) = o1;
        }
    }
}

// ===========================================================================
// Tensor-core flash attention v2:
//  - V stored ROW-major (like K); B-fragments via ldmatrix.x4.trans
//  - Q fragments hoisted to registers (loop-invariant)
//  - double-buffered K/V smem, ONE __syncthreads per key tile
// Smem elems: Q hi/lo 2x(128x72); KV 2 bufs x 4 regions x (64x72)
// ===========================================================================
#define AQHI 0
#define AQLO (128*72)
#define AKV  (2*128*72)
#define KVBUF (4*64*72)        // elems per buffer (KHI,KLO,VHI,VLO)
#define RKHI 0
#define RKLO (64*72)
#define RVHI (2*64*72)
#define RVLO (3*64*72)
#define ATT_SMEM ((AKV + 2*KVBUF) * 2)   // 110592 bytes

__global__ __launch_bounds__(256) void flash_attn_mma_kernel(
    const float* __restrict__ qkv,
    const int*   __restrict__ mask,
    __nv_bfloat16* __restrict__ Abf)
{
    extern __shared__ __nv_bfloat16 sm[];
    const int tid  = threadIdx.x;
    const int lane = tid & 31;
    const int w    = tid >> 5;
    const int bh = blockIdx.y, b = bh >> 4, h = bh & 15;
    const int q0 = blockIdx.x * 128;

    const float* qb = qkv + (size_t)(b * L_ + q0) * N1_ + h * DK_;
    const float* kb = qkv + (size_t)(b * L_) * N1_ + D_     + h * DK_;
    const float* vb = qkv + (size_t)(b * L_) * N1_ + 2 * D_ + h * DK_;

    // ---- Load Q tile (128x64 fp32) -> Qhi/Qlo smem
#pragma unroll
    for (int i = 0; i < 8; i++) {
        int idx = tid + i * 256;
        int row = idx >> 4, c4 = (idx & 15) * 4;
        float4 v = *reinterpret_cast<const float4*>(qb + (size_t)row * N1_ + c4);
        uint32_t h0, l0, h1, l1;
        pack_hilo(v.x, v.y, h0, l0);
        pack_hilo(v.z, v.w, h1, l1);
        uint32_t* qh = reinterpret_cast<uint32_t*>(sm + AQHI + row * 72 + c4);
        uint32_t* ql = reinterpret_cast<uint32_t*>(sm + AQLO + row * 72 + c4);
        qh[0] = h0; qh[1] = h1;
        ql[0] = l0; ql[1] = l1;
    }

    const uint32_t smB = smem_u32(sm);
    const uint32_t QHI2 = smB;
    const uint32_t QLO2 = smB + AQLO * 2;

    const uint32_t qRowByte = (uint32_t)(16 * w + (lane & 15)) * 144 + (uint32_t)(lane >> 4) * 16;
    const uint32_t kLaneByte = (uint32_t)lane * 144;
    // V trans addressing: lane -> matrix 2*(lane>>4) + ((lane>>3)&1), row lane&7
    const uint32_t vLaneRow = (uint32_t)(((lane >> 3) & 1) * 8 + (lane & 7)) * 144;
    const uint32_t vLaneCol = (uint32_t)(lane >> 4) * 16;

    // K/V prefetch regs (tile t)
    float4 kreg[4], vreg[4];
    auto LDGKV = [&](int t) {
        int k0 = t * 64;
#pragma unroll
        for (int i = 0; i < 4; i++) {
            int idx = tid + i * 256;
            int row = idx >> 4, c4 = (idx & 15) * 4;
            kreg[i] = *reinterpret_cast<const float4*>(kb + (size_t)(k0 + row) * N1_ + c4);
            vreg[i] = *reinterpret_cast<const float4*>(vb + (size_t)(k0 + row) * N1_ + c4);
        }
    };
    auto STSKV = [&](int buf) {
        __nv_bfloat16* base = sm + AKV + buf * KVBUF;
#pragma unroll
        for (int i = 0; i < 4; i++) {
            int idx = tid + i * 256;
            int row = idx >> 4, c4 = (idx & 15) * 4;
            uint32_t h0, l0, h1, l1;
            pack_hilo(kreg[i].x, kreg[i].y, h0, l0);
            pack_hilo(kreg[i].z, kreg[i].w, h1, l1);
            uint32_t* kh = reinterpret_cast<uint32_t*>(base + RKHI + row * 72 + c4);
            uint32_t* kl = reinterpret_cast<uint32_t*>(base + RKLO + row * 72 + c4);
            kh[0] = h0; kh[1] = h1;
            kl[0] = l0; kl[1] = l1;
            pack_hilo(vreg[i].x, vreg[i].y, h0, l0);
            pack_hilo(vreg[i].z, vreg[i].w, h1, l1);
            uint32_t* vh = reinterpret_cast<uint32_t*>(base + RVHI + row * 72 + c4);
            uint32_t* vl = reinterpret_cast<uint32_t*>(base + RVLO + row * 72 + c4);
            vh[0] = h0; vh[1] = h1;
            vl[0] = l0; vl[1] = l1;
        }
    };

    const int g  = lane >> 2;
    const int t4 = lane & 3;
    float m0 = -INFINITY, m1 = -INFINITY;
    float lr0 = 0.0f, lr1 = 0.0f;
    float oAcc[8][4];
#pragma unroll
    for (int j = 0; j < 8; j++)
#pragma unroll
        for (int q = 0; q < 4; q++) oAcc[j][q] = 0.0f;

    const int* mbase0 = mask + (size_t)b * L_ * L_ + (size_t)(q0 + 16 * w + g) * L_ + 2 * t4;
    const int* mbase1 = mbase0 + 8 * L_;

    LDGKV(0);
    __syncthreads();   // Q smem ready

    // ---- Hoist Q fragments (loop-invariant)
    uint32_t qH[4][4], qL[4][4];
#pragma unroll
    for (int s = 0; s < 4; s++) {
        LDMATRIX_X4(qH[s][0], qH[s][1], qH[s][2], qH[s][3], QHI2 + qRowByte + s * 32);
        LDMATRIX_X4(qL[s][0], qL[s][1], qL[s][2], qL[s][3], QLO2 + qRowByte + s * 32);
    }

    STSKV(0);
    __syncthreads();

    for (int t = 0; t < 32; t++) {
        const int cur = t & 1;
        if (t + 1 < 32) LDGKV(t + 1);

        const uint32_t KHI2 = smB + (AKV + cur * KVBUF + RKHI) * 2;
        const uint32_t KLO2 = smB + (AKV + cur * KVBUF + RKLO) * 2;
        const uint32_t VHI2 = smB + (AKV + cur * KVBUF + RVHI) * 2;
        const uint32_t VLO2 = smB + (AKV + cur * KVBUF + RVLO) * 2;

        // ---- S = Q' K'^T  (Qhi.Khi + Qlo.Khi + Qhi.Klo)
        float sAcc[8][4];
#pragma unroll
        for (int j = 0; j < 8; j++)
#pragma unroll
            for (int q = 0; q < 4; q++) sAcc[j][q] = 0.0f;

#pragma unroll
        for (int s = 0; s < 4; s++) {
            uint32_t k0h[8], k1h[8], k0l[8], k1l[8];
#pragma unroll
            for (int gg = 0; gg < 2; gg++) {
                uint32_t base = kLaneByte + gg * 4608 + s * 32;
                LDMATRIX_X4(k0h[gg*4+0], k0h[gg*4+1], k0h[gg*4+2], k0h[gg*4+3], KHI2 + base);
                LDMATRIX_X4(k1h[gg*4+0], k1h[gg*4+1], k1h[gg*4+2], k1h[gg*4+3], KHI2 + base + 16);
                LDMATRIX_X4(k0l[gg*4+0], k0l[gg*4+1], k0l[gg*4+2], k0l[gg*4+3], KLO2 + base);
                LDMATRIX_X4(k1l[gg*4+0], k1l[gg*4+1], k1l[gg*4+2], k1l[gg*4+3], KLO2 + base + 16);
            }
#pragma unroll
            for (int j = 0; j < 8; j++) {
                MMA_BF16(sAcc[j], qH[s], k0h[j], k1h[j]);
                MMA_BF16(sAcc[j], qL[s], k0h[j], k1h[j]);
                MMA_BF16(sAcc[j], qH[s], k0l[j], k1l[j]);
            }
        }

        // ---- mask + scale + online softmax
        const int k0 = t * 64;
        uint32_t mbits = 0;
        float mx0 = -INFINITY, mx1 = -INFINITY;
#pragma unroll
        for (int j = 0; j < 8; j++) {
            int2 mv0 = *reinterpret_cast<const int2*>(mbase0 + k0 + 8 * j);
            int2 mv1 = *reinterpret_cast<const int2*>(mbase1 + k0 + 8 * j);
            float v0 = mv0.x ? sAcc[j][0] * 0.125f : 0.0f;
            float v1 = mv0.y ? sAcc[j][1] * 0.125f : 0.0f;
            float v2 = mv1.x ? sAcc[j][2] * 0.125f : 0.0f;
            float v3 = mv1.y ? sAcc[j][3] * 0.125f : 0.0f;
            sAcc[j][0] = v0; sAcc[j][1] = v1; sAcc[j][2] = v2; sAcc[j][3] = v3;
            mbits |= (mv0.x ? 1u : 0u) << (4 * j)
                  |  (mv0.y ? 1u : 0u) << (4 * j + 1)
                  |  (mv1.x ? 1u : 0u) << (4 * j + 2)
                  |  (mv1.y ? 1u : 0u) << (4 * j + 3);
            mx0 = fmaxf(mx0, fmaxf(v0, v1));
            mx1 = fmaxf(mx1, fmaxf(v2, v3));
        }
        mx0 = fmaxf(mx0, __shfl_xor_sync(0xffffffffu, mx0, 1));
        mx0 = fmaxf(mx0, __shfl_xor_sync(0xffffffffu, mx0, 2));
        mx1 = fmaxf(mx1, __shfl_xor_sync(0xffffffffu, mx1, 1));
        mx1 = fmaxf(mx1, __shfl_xor_sync(0xffffffffu, mx1, 2));
        float mn0 = fmaxf(m0, mx0), mn1 = fmaxf(m1, mx1);

        float ls0 = 0.0f, ls1 = 0.0f;
#pragma unroll
        for (int j = 0; j < 8; j++) {
            float e0 = __expf(sAcc[j][0] - mn0);
            float e1 = __expf(sAcc[j][1] - mn0);
            float e2 = __expf(sAcc[j][2] - mn1);
            float e3 = __expf(sAcc[j][3] - mn1);
            ls0 += e0 + e1;
            ls1 += e2 + e3;
            sAcc[j][0] = ((mbits >> (4 * j))     & 1u) ? e0 : 0.0f;
            sAcc[j][1] = ((mbits >> (4 * j + 1)) & 1u) ? e1 : 0.0f;
            sAcc[j][2] = ((mbits >> (4 * j + 2)) & 1u) ? e2 : 0.0f;
            sAcc[j][3] = ((mbits >> (4 * j + 3)) & 1u) ? e3 : 0.0f;
        }
        ls0 += __shfl_xor_sync(0xffffffffu, ls0, 1);
        ls0 += __shfl_xor_sync(0xffffffffu, ls0, 2);
        ls1 += __shfl_xor_sync(0xffffffffu, ls1, 1);
        ls1 += __shfl_xor_sync(0xffffffffu, ls1, 2);

        float sc0 = __expf(m0 - mn0), sc1 = __expf(m1 - mn1);
        lr0 = lr0 * sc0 + ls0;
        lr1 = lr1 * sc1 + ls1;
        m0 = mn0; m1 = mn1;
#pragma unroll
        for (int j = 0; j < 8; j++) {
            oAcc[j][0] *= sc0; oAcc[j][1] *= sc0;
            oAcc[j][2] *= sc1; oAcc[j][3] *= sc1;
        }

        // Store next tile into the other buffer (overlaps with P.V below)
        if (t + 1 < 32) STSKV(cur ^ 1);

        // ---- O += P' V'  (V fragments via ldmatrix.trans; 3 split groups)
#pragma unroll
        for (int s = 0; s < 4; s++) {
            uint32_t pH[4], pL[4];
            pack_hilo(sAcc[2*s][0],   sAcc[2*s][1],   pH[0], pL[0]);
            pack_hilo(sAcc[2*s][2],   sAcc[2*s][3],   pH[1], pL[1]);
            pack_hilo(sAcc[2*s+1][0], sAcc[2*s+1][1], pH[2], pL[2]);
            pack_hilo(sAcc[2*s+1][2], sAcc[2*s+1][3], pH[3], pL[3]);
            uint32_t v0h[8], v1h[8], v0l[8], v1l[8];
            uint32_t rowB = (uint32_t)(s * 16) * 144 + vLaneRow + vLaneCol;
#pragma unroll
            for (int a = 0; a < 8; a += 2) {
                uint32_t addr = rowB + (uint32_t)a * 16;
                LDMATRIX_X4_T(v0h[a], v1h[a], v0h[a+1], v1h[a+1], VHI2 + addr);
                LDMATRIX_X4_T(v0l[a], v1l[a], v0l[a+1], v1l[a+1], VLO2 + addr);
            }
#pragma unroll
            for (int j = 0; j < 8; j++) {
                MMA_BF16(oAcc[j], pH, v0h[j], v1h[j]);
                MMA_BF16(oAcc[j], pL, v0h[j], v1h[j]);
                MMA_BF16(oAcc[j], pH, v0l[j], v1l[j]);
            }
        }
        __syncthreads();   // buf nxt fully written; buf cur reads done
    }

    // ---- Epilogue: normalize, write split-bf16 A' rows for GEMM2
    float i0 = 1.0f / lr0, i1 = 1.0f / lr1;
    __nv_bfloat16* ar0 = Abf + (size_t)(b * L_ + q0 + 16 * w + g) * K3_ + h * DK_ + 2 * t4;
    __nv_bfloat16* ar1 = ar0 + (size_t)8 * K3_;
#pragma unroll
    for (int j = 0; j < 8; j++) {
        uint32_t h0, l0, h1, l1;
        pack_hilo(oAcc[j][0] * i0, oAcc[j][1] * i0, h0, l0);
        pack_hilo(oAcc[j][2] * i1, oAcc[j][3] * i1, h1, l1);
        int c = 8 * j;
        *reinterpret_cast<uint32_t*>(ar0 + c)        = h0;
        *reinterpret_cast<uint32_t*>(ar0 + 1024 + c) = l0;
        *reinterpret_cast<uint32_t*>(ar0 + 2048 + c) = h0;
        *reinterpret_cast<uint32_t*>(ar1 + c)        = h1;
        *reinterpret_cast<uint32_t*>(ar1 + 1024 + c) = l1;
        *reinterpret_cast<uint32_t*>(ar1 + 2048 + c) = h1;
    }
}

// ===========================================================================
// kernel_launch
// ===========================================================================
extern "C" void kernel_launch(void* const* d_in, const int* in_sizes, int n_in,
                              void* d_out, int out_size)
{
    const float* inputs = (const float*)d_in[0];
    const int*   mask   = (const int*)d_in[1];
    const float* W1     = (const float*)d_in[2];
    const float* b1     = (const float*)d_in[3];
    const float* W2     = (const float*)d_in[4];
    const float* b2     = (const float*)d_in[5];
    float* out = (float*)d_out;

    float* qkv = nullptr;
    __nv_bfloat16* Abf = nullptr; __nv_bfloat16* Bbf = nullptr;
    cudaGetSymbolAddress((void**)&qkv, g_qkv);
    cudaGetSymbolAddress((void**)&Abf, g_Abf);
    cudaGetSymbolAddress((void**)&Bbf, g_Bbf);

    cudaFuncSetAttribute(flash_attn_mma_kernel,
                         cudaFuncAttributeMaxDynamicSharedMemorySize, ATT_SMEM);
    cudaFuncSetAttribute(mma_gemm_kernel,
                         cudaFuncAttributeMaxDynamicSharedMemorySize, G_SMEM_BYTES);

    // GEMM1: qkv = inputs @ W1 + b1   (split-bf16, K'=3072)
    pack_a_kernel<<<(M_ * D_ / 4) / 256, 256>>>(inputs, Abf);
    pack_bt_kernel<<<dim3(N1_ / 32, D_ / 32), dim3(32, 8)>>>(W1, Bbf, N1_);
    mma_gemm_kernel<<<dim3(N1_ / 128, M_ / 128), 256, G_SMEM_BYTES>>>(Abf, Bbf, b1, qkv, N1_);

    // Attention (tensor-core); writes split-bf16 A' for GEMM2 directly
    flash_attn_mma_kernel<<<dim3(L_ / 128, B_ * H_), 256, ATT_SMEM>>>(qkv, mask, Abf);

    // GEMM2: out = ctx @ W2 + b2
    pack_bt_kernel<<<dim3(D_ / 32, D_ / 32), dim3(32, 8)>>>(W2, Bbf, D_);
    mma_gemm_kernel<<<dim3(D_ / 128, M_ / 128), 256, G_SMEM_BYTES>>>(Abf, Bbf, b2, out, D_);
}